// round 5
// baseline (speedup 1.0000x reference)
#include <cuda_runtime.h>
#include <mma.h>

using namespace nvcuda;

#define NQ_MAX 50000
#define NC 128
#define NG 8
#define NS 16

// Padded by 128 rows: partial-tile wmma stores at the M edge write into the
// pad instead of the neighboring buffer.
__device__ float g_q[(NQ_MAX + 128) * NC];
__device__ float g_k[(NQ_MAX + 128) * NC];
__device__ float g_v[(NQ_MAX + 128) * NC];

__device__ __forceinline__ float to_tf32(float x) {
    float r;
    asm("cvt.rna.tf32.f32 %0, %1;" : "=f"(r) : "f"(x));
    return r;
}

// ---------------------------------------------------------------------------
// Projection GEMM (tf32 tensor cores), software-pipelined:
// prefetch next BK=32 tile into registers while wmma consumes current smem.
// Y[m,c] = sum_k X[m,k] * W[c,k]   (biases folded into attn kernel)
// Block tile 128x128, 8 warps: 4(M) x 2(N), warp tile 32x64.
// ---------------------------------------------------------------------------
#define LDA 36

__global__ void __launch_bounds__(256) proj_kernel(
    const float* __restrict__ x, const float* __restrict__ x2,
    const float* __restrict__ Wq, const float* __restrict__ Wk,
    const float* __restrict__ Wv,
    int n, int n2)
{
    const float *X, *W;
    float* Y;
    int M;
    if (blockIdx.y == 0)      { X = x;  W = Wq; Y = g_q; M = n;  }
    else if (blockIdx.y == 1) { X = x2; W = Wk; Y = g_k; M = n2; }
    else                      { X = x2; W = Wv; Y = g_v; M = n2; }

    __shared__ float As[128 * LDA];
    __shared__ float Bs[128 * LDA];

    const int t = threadIdx.x;
    const int block_m = blockIdx.x * 128;
    if (block_m >= M) return;

    const int warp = t >> 5;
    const int wm = (warp & 3) * 32;
    const int wn = (warp >> 2) * 64;

    // Per-thread load slots: 4 rows of A tile + 4 rows of B tile per stage.
    // lin = it*256 + t ; r = lin>>3 (0..127), c4 = (lin&7)*4 (0..28)
    const int r_  = t >> 3;
    const int c4_ = (t & 7) << 2;

    float4 pa[4], pb[4];

#define LOAD_STAGE(K0)                                                        \
    {                                                                         \
        _Pragma("unroll")                                                     \
        for (int it = 0; it < 4; it++) {                                      \
            int r = it * 32 + r_;                                             \
            int gr = block_m + r;                                             \
            pa[it] = make_float4(0.f, 0.f, 0.f, 0.f);                         \
            if (gr < M) pa[it] = *(const float4*)(X + (size_t)gr * 128 + (K0) + c4_); \
            pb[it] = *(const float4*)(W + (size_t)r * 128 + (K0) + c4_);      \
        }                                                                     \
    }

#define STORE_STAGE()                                                         \
    {                                                                         \
        _Pragma("unroll")                                                     \
        for (int it = 0; it < 4; it++) {                                      \
            int r = it * 32 + r_;                                             \
            As[r * LDA + c4_ + 0] = to_tf32(pa[it].x);                        \
            As[r * LDA + c4_ + 1] = to_tf32(pa[it].y);                        \
            As[r * LDA + c4_ + 2] = to_tf32(pa[it].z);                        \
            As[r * LDA + c4_ + 3] = to_tf32(pa[it].w);                        \
            Bs[r * LDA + c4_ + 0] = to_tf32(pb[it].x);                        \
            Bs[r * LDA + c4_ + 1] = to_tf32(pb[it].y);                        \
            Bs[r * LDA + c4_ + 2] = to_tf32(pb[it].z);                        \
            Bs[r * LDA + c4_ + 3] = to_tf32(pb[it].w);                        \
        }                                                                     \
    }

    wmma::fragment<wmma::accumulator, 16, 16, 8, float> acc[2][4];
#pragma unroll
    for (int i = 0; i < 2; i++)
#pragma unroll
        for (int j = 0; j < 4; j++) wmma::fill_fragment(acc[i][j], 0.0f);

    LOAD_STAGE(0);
    STORE_STAGE();
    __syncthreads();

#pragma unroll
    for (int stage = 0; stage < 4; stage++) {
        if (stage < 3) LOAD_STAGE((stage + 1) * 32);   // prefetch while computing

#pragma unroll
        for (int kk = 0; kk < 32; kk += 8) {
            wmma::fragment<wmma::matrix_a, 16, 16, 8, wmma::precision::tf32, wmma::row_major> a[2];
            wmma::fragment<wmma::matrix_b, 16, 16, 8, wmma::precision::tf32, wmma::col_major> b[4];
#pragma unroll
            for (int i = 0; i < 2; i++)
                wmma::load_matrix_sync(a[i], As + (wm + i * 16) * LDA + kk, LDA);
#pragma unroll
            for (int j = 0; j < 4; j++)
                wmma::load_matrix_sync(b[j], Bs + (wn + j * 16) * LDA + kk, LDA);
#pragma unroll
            for (int i = 0; i < 2; i++)
#pragma unroll
                for (int j = 0; j < 4; j++)
                    wmma::mma_sync(acc[i][j], a[i], b[j], acc[i][j]);
        }

        if (stage < 3) {
            __syncthreads();
            STORE_STAGE();
            __syncthreads();
        }
    }

#pragma unroll
    for (int i = 0; i < 2; i++)
#pragma unroll
        for (int j = 0; j < 4; j++)
            wmma::store_matrix_sync(
                Y + (size_t)(block_m + wm + i * 16) * 128 + wn + j * 16,
                acc[i][j], 128, wmma::mem_row_major);
}

// ---------------------------------------------------------------------------
// Fused gather + positional MLP + grouped attention, ONLINE SOFTMAX.
// One warp per query, lane l -> channels [4l,4l+4), group g = l>>2.
// logit = 0.25*(u + beta + prq*Bg + prk*(Sq + 16*prq)),
//   u (4-lane butterflied) = sum k_raw*q' + prq*sum k_raw
//   beta = sum bk*q' (group), Bg = sum_{c in g} bk, Sq = sum q' (group)
// Online update: m,d,o maintained per lane (replicated within group).
// out = o/d + bv.
// ---------------------------------------------------------------------------
__global__ void __launch_bounds__(256, 5) attn_kernel(
    const float* __restrict__ p, const float* __restrict__ p2,
    const int* __restrict__ idx,
    const float* __restrict__ bq, const float* __restrict__ bk,
    const float* __restrict__ bv,
    const float* __restrict__ W1, const float* __restrict__ b1,
    const float* __restrict__ bng, const float* __restrict__ bnb,
    const float* __restrict__ bnm, const float* __restrict__ bnv,
    const float* __restrict__ W2, const float* __restrict__ b2,
    float* __restrict__ out, int n)
{
    __shared__ float sA[9];
    __shared__ float sc[3];
    __shared__ float sW2[16][3];
    __shared__ float sb2[16];
    __shared__ float sBg[8];

    const int t = threadIdx.x;
    if (t < 9) {
        int r = t / 3;
        float s = bng[r] * rsqrtf(bnv[r] + 1e-5f);
        sA[t] = s * W1[t];
    }
    if (t < 3) sc[t] = bng[t] * rsqrtf(bnv[t] + 1e-5f) * (b1[t] - bnm[t]) + bnb[t];
    if (t < 48) sW2[t / 3][t % 3] = W2[t];
    if (t < 16) sb2[t] = b2[t];
    if (t < 8) {
        float s = 0.f;
#pragma unroll
        for (int c = 0; c < 16; c++) s += bk[t * 16 + c];
        sBg[t] = s;
    }
    __syncthreads();

    const int warp = t >> 5;
    const int lane = t & 31;
    const int i = blockIdx.x * 8 + warp;
    if (i >= n) return;

    const int g = lane >> 2;
    const float w2q0 = sW2[g][0], w2q1 = sW2[g][1], w2q2 = sW2[g][2], b2q = sb2[g];
    const float w2k0 = sW2[8 + g][0], w2k1 = sW2[8 + g][1], w2k2 = sW2[8 + g][2], b2k = sb2[8 + g];
    const float Bg = sBg[g];

    float4 q4 = *(const float4*)(g_q + (size_t)i * 128 + lane * 4);
    {
        const float4 bq4 = *(const float4*)(bq + lane * 4);
        q4.x += bq4.x; q4.y += bq4.y; q4.z += bq4.z; q4.w += bq4.w;
    }

    float qs, beta;
    {
        const float4 bk4 = *(const float4*)(bk + lane * 4);
        qs   = q4.x + q4.y + q4.z + q4.w;
        beta = bk4.x * q4.x + bk4.y * q4.y + bk4.z * q4.z + bk4.w * q4.w;
        qs   += __shfl_xor_sync(0xffffffffu, qs, 1);
        beta += __shfl_xor_sync(0xffffffffu, beta, 1);
        qs   += __shfl_xor_sync(0xffffffffu, qs, 2);
        beta += __shfl_xor_sync(0xffffffffu, beta, 2);
    }

    const float px = p[i * 3 + 0], py = p[i * 3 + 1], pz = p[i * 3 + 2];

    float m = -1e30f, d = 0.f;
    float4 o = make_float4(0.f, 0.f, 0.f, 0.f);

    const int4* ip = (const int4*)(idx + (size_t)i * 16);
#pragma unroll
    for (int s4 = 0; s4 < 4; s4++) {
        const int4 nb4 = ip[s4];
        const int nbs[4] = {nb4.x, nb4.y, nb4.z, nb4.w};
#pragma unroll
        for (int ss = 0; ss < 4; ss++) {
            const int j = nbs[ss];
            const float4 k4 = *(const float4*)(g_k + (size_t)j * 128 + lane * 4);
            const float4 v4 = *(const float4*)(g_v + (size_t)j * 128 + lane * 4);

            float kq = k4.x * q4.x + k4.y * q4.y + k4.z * q4.z + k4.w * q4.w;
            float ks = k4.x + k4.y + k4.z + k4.w;

            const float rx = p2[j * 3 + 0] - px;
            const float ry = p2[j * 3 + 1] - py;
            const float rz = p2[j * 3 + 2] - pz;
            const float h0 = fmaxf(sA[0] * rx + sA[1] * ry + sA[2] * rz + sc[0], 0.f);
            const float h1 = fmaxf(sA[3] * rx + sA[4] * ry + sA[5] * rz + sc[1], 0.f);
            const float h2 = fmaxf(sA[6] * rx + sA[7] * ry + sA[8] * rz + sc[2], 0.f);
            const float prq = w2q0 * h0 + w2q1 * h1 + w2q2 * h2 + b2q;
            const float prk = w2k0 * h0 + w2k1 * h1 + w2k2 * h2 + b2k;

            float u = fmaf(prq, ks, kq);
            u += __shfl_xor_sync(0xffffffffu, u, 1);
            u += __shfl_xor_sync(0xffffffffu, u, 2);

            const float logit = 0.25f * (u + beta + prq * Bg + prk * fmaf(16.f, prq, qs));

            // online softmax update (state replicated across the 4 group lanes)
            const float nm = fmaxf(m, logit);
            const float scale = __expf(m - nm);
            const float e = __expf(logit - nm);
            m = nm;
            d = d * scale + e;
            o.x = fmaf(e, v4.x, o.x * scale);
            o.y = fmaf(e, v4.y, o.y * scale);
            o.z = fmaf(e, v4.z, o.z * scale);
            o.w = fmaf(e, v4.w, o.w * scale);
        }
    }

    const float inv = 1.f / d;
    const float4 bv4 = *(const float4*)(bv + lane * 4);
    o.x = fmaf(o.x, inv, bv4.x);
    o.y = fmaf(o.y, inv, bv4.y);
    o.z = fmaf(o.z, inv, bv4.z);
    o.w = fmaf(o.w, inv, bv4.w);
    *(float4*)(out + (size_t)i * 128 + lane * 4) = o;
}

extern "C" void kernel_launch(void* const* d_in, const int* in_sizes, int n_in,
                              void* d_out, int out_size)
{
    const float* p   = (const float*)d_in[0];
    const float* x   = (const float*)d_in[1];
    const float* p2  = (const float*)d_in[2];
    const float* x2  = (const float*)d_in[3];
    const int*   idx = (const int*)d_in[4];
    const float* Wq  = (const float*)d_in[5];
    const float* bq  = (const float*)d_in[6];
    const float* Wk  = (const float*)d_in[7];
    const float* bk  = (const float*)d_in[8];
    const float* Wv  = (const float*)d_in[9];
    const float* bv  = (const float*)d_in[10];
    const float* W1  = (const float*)d_in[11];
    const float* b1  = (const float*)d_in[12];
    const float* bng = (const float*)d_in[13];
    const float* bnb = (const float*)d_in[14];
    const float* bnm = (const float*)d_in[15];
    const float* bnv = (const float*)d_in[16];
    const float* W2  = (const float*)d_in[17];
    const float* b2  = (const float*)d_in[18];
    float* out = (float*)d_out;

    const int n  = in_sizes[1] / NC;
    const int n2 = in_sizes[3] / NC;
    const int mmax = n > n2 ? n : n2;

    dim3 pg((mmax + 127) / 128, 3);
    proj_kernel<<<pg, 256>>>(x, x2, Wq, Wk, Wv, n, n2);
    attn_kernel<<<(n + 7) / 8, 256>>>(p, p2, idx, bq, bk, bv,
                                      W1, b1, bng, bnb, bnm, bnv,
                                      W2, b2, out, n);
}